// round 15
// baseline (speedup 1.0000x reference)
#include <cuda_runtime.h>
#include <cuda_fp16.h>

#define S_LEN   2048
#define B_SZ    2
#define DM      1024
#define NH      16
#define HD      64
#define HK      1024            // NH*HD
#define MROWS   (B_SZ*S_LEN)    // 4096

// ---------------- scratch (static device arrays; no allocation) -------------
__device__ float g_q[B_SZ*NH*S_LEN*HD];   // (b,h,s,k)
__device__ float g_k[B_SZ*NH*S_LEN*HD];
__device__ float g_v[B_SZ*NH*S_LEN*HD];
__device__ float g_o[MROWS*HK];           // (b,s,hk)

// ---------------- helpers ----------------------------------------------------
__device__ __forceinline__ unsigned h2pack(float a, float b) {
    __half2 t = __floats2half2_rn(a, b);
    return *(unsigned*)&t;
}

__device__ __forceinline__ void mma_f16(float* c, const unsigned* a, const unsigned* b) {
    asm volatile(
        "mma.sync.aligned.m16n8k16.row.col.f32.f16.f16.f32 "
        "{%0,%1,%2,%3}, {%4,%5,%6,%7}, {%8,%9}, {%0,%1,%2,%3};\n"
        : "+f"(c[0]), "+f"(c[1]), "+f"(c[2]), "+f"(c[3])
        : "r"(a[0]), "r"(a[1]), "r"(a[2]), "r"(a[3]),
          "r"(b[0]), "r"(b[1]));
}

// =====================================================================
// FP16 GEMM v2: CTA 128x128, 256 threads (8 warps 2x4), warp tile 64x32,
// K-chunk 16, double-buffered. acc=64 regs/thread -> 16 warps/SM.
// Smem: As[k2(8)][m(128)], Bs[k2(8)][n(128)] packed half2 words.
// =====================================================================
#define GS 132

#define G2_LOAD(kbase) do {                                                   \
    _Pragma("unroll")                                                         \
    for (int p = 0; p < 2; p++) {                                             \
        int la = p*256 + tid;                                                 \
        av[p] = *(const float4*)&aP[(size_t)(la >> 2) * KROW + (kbase) + (la & 3) * 4]; \
    }                                                                         \
    {                                                                         \
        int kr2 = tid >> 5, nc = (tid & 31) * 4;                              \
        bv0 = *(const float4*)&bP[(size_t)((kbase) + 2*kr2    ) * NROW + nc]; \
        bv1 = *(const float4*)&bP[(size_t)((kbase) + 2*kr2 + 1) * NROW + nc]; \
    }                                                                         \
} while (0)

#define G2_STAGE(buf) do {                                                    \
    _Pragma("unroll")                                                         \
    for (int p = 0; p < 2; p++) {                                             \
        int la = p*256 + tid;                                                 \
        int row = la >> 2, kc = (la & 3) * 4;                                 \
        As[buf][(kc>>1)  ][row] = h2pack(av[p].x, av[p].y);                   \
        As[buf][(kc>>1)+1][row] = h2pack(av[p].z, av[p].w);                   \
    }                                                                         \
    {                                                                         \
        int kr2 = tid >> 5, nc = (tid & 31) * 4;                              \
        Bs[buf][kr2][nc+0] = h2pack(bv0.x, bv1.x);                            \
        Bs[buf][kr2][nc+1] = h2pack(bv0.y, bv1.y);                            \
        Bs[buf][kr2][nc+2] = h2pack(bv0.z, bv1.z);                            \
        Bs[buf][kr2][nc+3] = h2pack(bv0.w, bv1.w);                            \
    }                                                                         \
} while (0)

#define G2_MMA(buf) do {                                                      \
    unsigned af[4][4], bf[4][2];                                              \
    _Pragma("unroll")                                                         \
    for (int i = 0; i < 4; i++) {                                             \
        int mb = wm*64 + i*16;                                                \
        af[i][0] = As[buf][tig  ][mb+g];                                      \
        af[i][1] = As[buf][tig  ][mb+g+8];                                    \
        af[i][2] = As[buf][tig+4][mb+g];                                      \
        af[i][3] = As[buf][tig+4][mb+g+8];                                    \
    }                                                                         \
    _Pragma("unroll")                                                         \
    for (int j = 0; j < 4; j++) {                                             \
        int nb = wn*32 + j*8;                                                 \
        bf[j][0] = Bs[buf][tig  ][nb+g];                                      \
        bf[j][1] = Bs[buf][tig+4][nb+g];                                      \
    }                                                                         \
    _Pragma("unroll")                                                         \
    for (int i = 0; i < 4; i++)                                               \
        _Pragma("unroll")                                                     \
        for (int j = 0; j < 4; j++)                                           \
            mma_f16(acc[i][j], af[i], bf[j]);                                 \
} while (0)

__global__ __launch_bounds__(256, 2)
void qkv_gemm_f16(const float* __restrict__ x,
                  const float* __restrict__ Wq, const float* __restrict__ bq,
                  const float* __restrict__ Wk, const float* __restrict__ bk,
                  const float* __restrict__ Wv, const float* __restrict__ bv)
{
    __shared__ unsigned As[2][8][GS];
    __shared__ unsigned Bs[2][8][GS];

    const float* W; const float* bias; float* out;
    int z = blockIdx.z;
    if (z == 0)      { W = Wq; bias = bq; out = g_q; }
    else if (z == 1) { W = Wk; bias = bk; out = g_k; }
    else             { W = Wv; bias = bv; out = g_v; }

    const int KROW = DM, NROW = HK;
    int tid  = threadIdx.x;
    int w    = tid >> 5, lane = tid & 31;
    int g    = lane >> 2, tig = lane & 3;
    int wm   = w & 1, wn = w >> 1;
    int m0   = blockIdx.y * 128, n0 = blockIdx.x * 128;

    const float* aP = x + (size_t)m0 * KROW;
    const float* bP = W + n0;

    float4 av[2], bv0, bv1;
    float acc[4][4][4] = {};

    G2_LOAD(0);
    G2_STAGE(0);
    __syncthreads();

    for (int k0 = 0; k0 < DM; k0 += 16) {
        int cur = (k0 >> 4) & 1;
        bool more = (k0 + 16 < DM);
        if (more) G2_LOAD(k0 + 16);
        G2_MMA(cur);
        if (more) {
            if (cur) G2_STAGE(0); else G2_STAGE(1);
        }
        __syncthreads();
    }

    #pragma unroll
    for (int i = 0; i < 4; i++) {
        int r0m = m0 + wm*64 + i*16 + g;
        #pragma unroll
        for (int j = 0; j < 4; j++) {
            int n = n0 + wn*32 + j*8 + tig*2;
            int h = n >> 6, kd = n & 63;
            float bvv0 = bias[n], bvv1 = bias[n+1];
            int b0i = r0m >> 11, s0 = r0m & (S_LEN-1);
            size_t base0 = (((size_t)(b0i*NH + h) * S_LEN + s0) << 6) + kd;
            out[base0]     = acc[i][j][0] + bvv0;
            out[base0 + 1] = acc[i][j][1] + bvv1;
            int r1m = r0m + 8;
            int b1i = r1m >> 11, s1 = r1m & (S_LEN-1);
            size_t base1 = (((size_t)(b1i*NH + h) * S_LEN + s1) << 6) + kd;
            out[base1]     = acc[i][j][2] + bvv0;
            out[base1 + 1] = acc[i][j][3] + bvv1;
        }
    }
}

__global__ __launch_bounds__(256, 2)
void out_gemm_f16(const float* __restrict__ Wo,
                  const float* __restrict__ bo,
                  float* __restrict__ C)
{
    __shared__ unsigned As[2][8][GS];
    __shared__ unsigned Bs[2][8][GS];

    const int KROW = HK, NROW = DM;
    int tid  = threadIdx.x;
    int w    = tid >> 5, lane = tid & 31;
    int g    = lane >> 2, tig = lane & 3;
    int wm   = w & 1, wn = w >> 1;
    int m0   = blockIdx.y * 128, n0 = blockIdx.x * 128;

    const float* aP = g_o + (size_t)m0 * KROW;
    const float* bP = Wo + n0;

    float4 av[2], bv0, bv1;
    float acc[4][4][4] = {};

    G2_LOAD(0);
    G2_STAGE(0);
    __syncthreads();

    for (int k0 = 0; k0 < HK; k0 += 16) {
        int cur = (k0 >> 4) & 1;
        bool more = (k0 + 16 < HK);
        if (more) G2_LOAD(k0 + 16);
        G2_MMA(cur);
        if (more) {
            if (cur) G2_STAGE(0); else G2_STAGE(1);
        }
        __syncthreads();
    }

    #pragma unroll
    for (int i = 0; i < 4; i++) {
        int r0m = m0 + wm*64 + i*16 + g;
        #pragma unroll
        for (int j = 0; j < 4; j++) {
            int n = n0 + wn*32 + j*8 + tig*2;
            float bvv0 = bo[n], bvv1 = bo[n+1];
            float2 o0 = make_float2(acc[i][j][0] + bvv0, acc[i][j][1] + bvv1);
            float2 o1 = make_float2(acc[i][j][2] + bvv0, acc[i][j][3] + bvv1);
            *(float2*)&C[(size_t)r0m * DM + n]       = o0;
            *(float2*)&C[(size_t)(r0m+8) * DM + n]   = o1;
        }
    }
}

// =====================================================================
// Flash attention, FP16 m16n8k16 MMA (exact R14 state).
// =====================================================================
#define ATTN_SMEM (12288 * 4)
#define QSCALE 0.1803368801111204f   // 0.125 * log2(e)

#define ATTN_STAGE(bb, t0) do {                                               \
    _Pragma("unroll")                                                         \
    for (int f = 0; f < 8; f++) {                                             \
        int linear = f*128 + tid;                                             \
        int j = linear >> 4, d0 = (linear & 15) * 4;                          \
        float4 kv = *(const float4*)&kp[(size_t)((t0)+j)*HD + d0];            \
        {                                                                     \
            int kt = d0 >> 4, r = (d0 >> 3) & 1;                              \
            int nt = j >> 3;                                                  \
            int laneK = ((j & 7) << 2) + ((d0 & 7) >> 1);                     \
            unsigned* dst = &su[(bb)*2048 + ((((kt<<3)+nt)<<5) + laneK)*2 + r]; \
            dst[0] = h2pack(kv.x, kv.y);                                      \
            dst[2] = h2pack(kv.z, kv.w);                                      \
        }                                                                     \
        float4 vv = *(const float4*)&vp[(size_t)((t0)+j)*HD + d0];            \
        {                                                                     \
            int ktv = j >> 4, rv = (j >> 3) & 1;                              \
            int pairv = (j & 7) >> 1, ev = j & 1;                             \
            int ntv = d0 >> 3;                                                \
            __half* hb = (__half*)(su + 4096 + (bb)*2048);                    \
            int base = (((((ktv<<3)+ntv)<<5) + ((d0&7)<<2) + pairv)*2 + rv)*2 + ev; \
            hb[base     ] = __float2half(vv.x);                               \
            hb[base + 16] = __float2half(vv.y);                               \
            hb[base + 32] = __float2half(vv.z);                               \
            hb[base + 48] = __float2half(vv.w);                               \
        }                                                                     \
    }                                                                         \
} while (0)

__global__ __launch_bounds__(128, 2)
void attn_mma()
{
    extern __shared__ unsigned su[];
    unsigned* PA = su + 8192;

    int tid  = threadIdx.x;
    int w    = tid >> 5, lane = tid & 31;
    int g    = lane >> 2, tig = lane & 3;
    int bh   = blockIdx.y;
    int b    = bh >> 4, h = bh & 15;
    int q0   = blockIdx.x * 128;

    const float* qp = g_q + (size_t)bh * S_LEN * HD;
    const float* kp = g_k + (size_t)bh * S_LEN * HD;
    const float* vp = g_v + (size_t)bh * S_LEN * HD;

    // ---- stage Q (scratch overlay on KB/VB), build prescaled fp16 A-frags ----
    float* Qs = (float*)su;    // 128x64 f32 = 32 KB
    #pragma unroll
    for (int it = 0; it < 16; it++) {
        int linear = it*128 + tid;
        int j = linear >> 4, d0 = (linear & 15) * 4;
        *(float4*)&Qs[j*64 + d0] = *(const float4*)&qp[(size_t)(q0 + j)*HD + d0];
    }
    __syncthreads();
    unsigned qf[2][4][4];   // [mi][kt][reg]
    #pragma unroll
    for (int mi = 0; mi < 2; mi++) {
        int rbase = 32*w + 16*mi;
        #pragma unroll
        for (int kt = 0; kt < 4; kt++) {
            const float* r0p = &Qs[(rbase+g  )*64 + kt*16];
            const float* r1p = &Qs[(rbase+g+8)*64 + kt*16];
            qf[mi][kt][0] = h2pack(r0p[2*tig  ]*QSCALE, r0p[2*tig+1]*QSCALE);
            qf[mi][kt][1] = h2pack(r1p[2*tig  ]*QSCALE, r1p[2*tig+1]*QSCALE);
            qf[mi][kt][2] = h2pack(r0p[8+2*tig]*QSCALE, r0p[8+2*tig+1]*QSCALE);
            qf[mi][kt][3] = h2pack(r1p[8+2*tig]*QSCALE, r1p[8+2*tig+1]*QSCALE);
        }
    }
    __syncthreads();

    ATTN_STAGE(0, 0);

    float o_acc[2][8][4] = {};
    float mrun[2][2], lrun[2][2];
    #pragma unroll
    for (int mi = 0; mi < 2; mi++) {
        mrun[mi][0] = -1e30f; mrun[mi][1] = -1e30f;
        lrun[mi][0] = 0.f;    lrun[mi][1] = 0.f;
    }

    #pragma unroll 1
    for (int it = 0; it < S_LEN/64; it++) {
        int cur = it & 1;
        __syncthreads();

        // ---- S = Q @ K^T ----
        const unsigned* KBc = su + cur*2048;
        float s[2][8][4] = {};
        #pragma unroll
        for (int kt = 0; kt < 4; kt++) {
            #pragma unroll
            for (int nt = 0; nt < 8; nt++) {
                unsigned b2[2];
                *(uint2*)b2 = *(const uint2*)&KBc[((((kt<<3)+nt)<<5) + lane)*2];
                mma_f16(s[0][nt], qf[0][kt], b2);
                mma_f16(s[1][nt], qf[1][kt], b2);
            }
        }

        // ---- online softmax (exp2 domain, quad-local), pack P to fp16 ----
        unsigned* paw = PA + w*1024;
        #pragma unroll
        for (int mi = 0; mi < 2; mi++) {
            float mx0 = mrun[mi][0], mx1 = mrun[mi][1];
            #pragma unroll
            for (int nt = 0; nt < 8; nt++) {
                mx0 = fmaxf(mx0, fmaxf(s[mi][nt][0], s[mi][nt][1]));
                mx1 = fmaxf(mx1, fmaxf(s[mi][nt][2], s[mi][nt][3]));
            }
            mx0 = fmaxf(mx0, __shfl_xor_sync(0xffffffffu, mx0, 1));
            mx0 = fmaxf(mx0, __shfl_xor_sync(0xffffffffu, mx0, 2));
            mx1 = fmaxf(mx1, __shfl_xor_sync(0xffffffffu, mx1, 1));
            mx1 = fmaxf(mx1, __shfl_xor_sync(0xffffffffu, mx1, 2));

            float alpha0 = exp2f(mrun[mi][0] - mx0);
            float alpha1 = exp2f(mrun[mi][1] - mx1);
            mrun[mi][0] = mx0; mrun[mi][1] = mx1;

            float sum0 = 0.f, sum1 = 0.f;
            unsigned* pam = paw + mi*512;
            #pragma unroll
            for (int nt = 0; nt < 8; nt++) {
                float p00 = exp2f(s[mi][nt][0] - mx0);
                float p01 = exp2f(s[mi][nt][1] - mx0);
                float p10 = exp2f(s[mi][nt][2] - mx1);
                float p11 = exp2f(s[mi][nt][3] - mx1);
                sum0 += p00 + p01;
                sum1 += p10 + p11;
                pam[((nt<<4) + g    )*4 + tig] = h2pack(p00, p01);
                pam[((nt<<4) + g + 8)*4 + tig] = h2pack(p10, p11);
            }
            sum0 += __shfl_xor_sync(0xffffffffu, sum0, 1);
            sum0 += __shfl_xor_sync(0xffffffffu, sum0, 2);
            sum1 += __shfl_xor_sync(0xffffffffu, sum1, 1);
            sum1 += __shfl_xor_sync(0xffffffffu, sum1, 2);
            lrun[mi][0] = lrun[mi][0]*alpha0 + sum0;
            lrun[mi][1] = lrun[mi][1]*alpha1 + sum1;

            #pragma unroll
            for (int nt = 0; nt < 8; nt++) {
                o_acc[mi][nt][0] *= alpha0; o_acc[mi][nt][1] *= alpha0;
                o_acc[mi][nt][2] *= alpha1; o_acc[mi][nt][3] *= alpha1;
            }
        }
        __syncwarp();

        // ---- O += P @ V ----
        const unsigned* VBc = su + 4096 + cur*2048;
        #pragma unroll
        for (int kt = 0; kt < 4; kt++) {
            unsigned pa0[4], pa1[4];
            pa0[0] = paw[(((2*kt  )<<4) + g    )*4 + tig];
            pa0[1] = paw[(((2*kt  )<<4) + g + 8)*4 + tig];
            pa0[2] = paw[(((2*kt+1)<<4) + g    )*4 + tig];
            pa0[3] = paw[(((2*kt+1)<<4) + g + 8)*4 + tig];
            pa1[0] = paw[512 + (((2*kt  )<<4) + g    )*4 + tig];
            pa1[1] = paw[512 + (((2*kt  )<<4) + g + 8)*4 + tig];
            pa1[2] = paw[512 + (((2*kt+1)<<4) + g    )*4 + tig];
            pa1[3] = paw[512 + (((2*kt+1)<<4) + g + 8)*4 + tig];
            #pragma unroll
            for (int nt = 0; nt < 8; nt++) {
                unsigned b2[2];
                *(uint2*)b2 = *(const uint2*)&VBc[((((kt<<3)+nt)<<5) + lane)*2];
                mma_f16(o_acc[0][nt], pa0, b2);
                mma_f16(o_acc[1][nt], pa1, b2);
            }
        }

        if (it + 1 < S_LEN/64) {
            ATTN_STAGE(1 - cur, (it + 1) * 64);
        }
    }

    // ---- epilogue ----
    #pragma unroll
    for (int mi = 0; mi < 2; mi++) {
        float inv0 = 1.0f / lrun[mi][0], inv1 = 1.0f / lrun[mi][1];
        int r0 = q0 + 32*w + 16*mi + g, r1 = r0 + 8;
        #pragma unroll
        for (int nt = 0; nt < 8; nt++) {
            int c = nt*8 + 2*tig;
            *(float2*)&g_o[(size_t)(b*S_LEN + r0)*HK + h*64 + c] =
                make_float2(o_acc[mi][nt][0]*inv0, o_acc[mi][nt][1]*inv0);
            *(float2*)&g_o[(size_t)(b*S_LEN + r1)*HK + h*64 + c] =
                make_float2(o_acc[mi][nt][2]*inv1, o_acc[mi][nt][3]*inv1);
        }
    }
}

// =====================================================================
extern "C" void kernel_launch(void* const* d_in, const int* in_sizes, int n_in,
                              void* d_out, int out_size)
{
    (void)in_sizes; (void)n_in; (void)out_size;
    const float* x  = (const float*)d_in[0];
    const float* Wq = (const float*)d_in[1];
    const float* bq = (const float*)d_in[2];
    const float* Wk = (const float*)d_in[3];
    const float* bk = (const float*)d_in[4];
    const float* Wv = (const float*)d_in[5];
    const float* bv = (const float*)d_in[6];
    const float* Wo = (const float*)d_in[7];
    const float* bo = (const float*)d_in[8];
    float* out = (float*)d_out;

    qkv_gemm_f16<<<dim3(HK/128, MROWS/128, 3), 256>>>(x, Wq, bq, Wk, bk, Wv, bv);

    cudaFuncSetAttribute(attn_mma, cudaFuncAttributeMaxDynamicSharedMemorySize, ATTN_SMEM);
    attn_mma<<<dim3(S_LEN/128, B_SZ*NH), 128, ATTN_SMEM>>>();

    out_gemm_f16<<<dim3(DM/128, MROWS/128), 256>>>(Wo, bo, out);
}

// round 16
// speedup vs baseline: 1.0285x; 1.0285x over previous
#include <cuda_runtime.h>
#include <cuda_fp16.h>

#define S_LEN   2048
#define B_SZ    2
#define DM      1024
#define NH      16
#define HD      64
#define HK      1024            // NH*HD
#define MROWS   (B_SZ*S_LEN)    // 4096

// ---------------- scratch (static device arrays; no allocation) -------------
__device__ float g_q[B_SZ*NH*S_LEN*HD];   // (b,h,s,k)
__device__ float g_k[B_SZ*NH*S_LEN*HD];
__device__ float g_v[B_SZ*NH*S_LEN*HD];
__device__ float g_o[MROWS*HK];           // (b,s,hk)

// ---------------- helpers ----------------------------------------------------
__device__ __forceinline__ unsigned h2pack(float a, float b) {
    __half2 t = __floats2half2_rn(a, b);
    return *(unsigned*)&t;
}

__device__ __forceinline__ void mma_f16(float* c, const unsigned* a, const unsigned* b) {
    asm volatile(
        "mma.sync.aligned.m16n8k16.row.col.f32.f16.f16.f32 "
        "{%0,%1,%2,%3}, {%4,%5,%6,%7}, {%8,%9}, {%0,%1,%2,%3};\n"
        : "+f"(c[0]), "+f"(c[1]), "+f"(c[2]), "+f"(c[3])
        : "r"(a[0]), "r"(a[1]), "r"(a[2]), "r"(a[3]),
          "r"(b[0]), "r"(b[1]));
}

// =====================================================================
// FP16 GEMM (R14 checkpoint): CTA 128x128, 128 threads (4 warps 2x2),
// warp tile 64x64, K-chunk 16, double-buffered.
// =====================================================================
#define GS 132

#define GEMM_STAGE16(buf) do {                                                \
    _Pragma("unroll")                                                         \
    for (int p = 0; p < 4; p++) {                                             \
        int la = p*128 + tid;                                                 \
        int row = la >> 2, kc = (la & 3) * 4;                                 \
        As[buf][(kc>>1)  ][row] = h2pack(av[p].x, av[p].y);                   \
        As[buf][(kc>>1)+1][row] = h2pack(av[p].z, av[p].w);                   \
    }                                                                         \
    _Pragma("unroll")                                                         \
    for (int p = 0; p < 2; p++) {                                             \
        int lb = p*128 + tid;                                                 \
        int kr2 = lb >> 5, nc = (lb & 31) * 4;                                \
        Bs[buf][kr2][nc+0] = h2pack(bv0[p].x, bv1[p].x);                      \
        Bs[buf][kr2][nc+1] = h2pack(bv0[p].y, bv1[p].y);                      \
        Bs[buf][kr2][nc+2] = h2pack(bv0[p].z, bv1[p].z);                      \
        Bs[buf][kr2][nc+3] = h2pack(bv0[p].w, bv1[p].w);                      \
    }                                                                         \
} while (0)

#define GEMM_LOAD16(kbase) do {                                               \
    _Pragma("unroll")                                                         \
    for (int p = 0; p < 4; p++) {                                             \
        int la = p*128 + tid;                                                 \
        av[p] = *(const float4*)&aP[(size_t)(la >> 2) * KROW + (kbase) + (la & 3) * 4]; \
    }                                                                         \
    _Pragma("unroll")                                                         \
    for (int p = 0; p < 2; p++) {                                             \
        int lb = p*128 + tid;                                                 \
        int kr2 = lb >> 5, nc = (lb & 31) * 4;                                \
        bv0[p] = *(const float4*)&bP[(size_t)((kbase) + 2*kr2    ) * NROW + nc]; \
        bv1[p] = *(const float4*)&bP[(size_t)((kbase) + 2*kr2 + 1) * NROW + nc]; \
    }                                                                         \
} while (0)

#define GEMM_MMA16(buf) do {                                                  \
    unsigned af[4][4], bf[8][2];                                              \
    _Pragma("unroll")                                                         \
    for (int i = 0; i < 4; i++) {                                             \
        int mb = wm*64 + i*16;                                                \
        af[i][0] = As[buf][tig  ][mb+g];                                      \
        af[i][1] = As[buf][tig  ][mb+g+8];                                    \
        af[i][2] = As[buf][tig+4][mb+g];                                      \
        af[i][3] = As[buf][tig+4][mb+g+8];                                    \
    }                                                                         \
    _Pragma("unroll")                                                         \
    for (int j = 0; j < 8; j++) {                                             \
        int nb = wn*64 + j*8;                                                 \
        bf[j][0] = Bs[buf][tig  ][nb+g];                                      \
        bf[j][1] = Bs[buf][tig+4][nb+g];                                      \
    }                                                                         \
    _Pragma("unroll")                                                         \
    for (int i = 0; i < 4; i++)                                               \
        _Pragma("unroll")                                                     \
        for (int j = 0; j < 8; j++)                                           \
            mma_f16(acc[i][j], af[i], bf[j]);                                 \
} while (0)

__global__ __launch_bounds__(128, 2)
void qkv_gemm_f16(const float* __restrict__ x,
                  const float* __restrict__ Wq, const float* __restrict__ bq,
                  const float* __restrict__ Wk, const float* __restrict__ bk,
                  const float* __restrict__ Wv, const float* __restrict__ bv)
{
    __shared__ unsigned As[2][8][GS];
    __shared__ unsigned Bs[2][8][GS];

    const float* W; const float* bias; float* out;
    int z = blockIdx.z;
    if (z == 0)      { W = Wq; bias = bq; out = g_q; }
    else if (z == 1) { W = Wk; bias = bk; out = g_k; }
    else             { W = Wv; bias = bv; out = g_v; }

    const int KROW = DM, NROW = HK;
    int tid  = threadIdx.x;
    int w    = tid >> 5, lane = tid & 31;
    int g    = lane >> 2, tig = lane & 3;
    int wm   = w & 1, wn = w >> 1;
    int m0   = blockIdx.y * 128, n0 = blockIdx.x * 128;

    const float* aP = x + (size_t)m0 * KROW;
    const float* bP = W + n0;

    float4 av[4], bv0[2], bv1[2];
    float acc[4][8][4] = {};

    GEMM_LOAD16(0);
    GEMM_STAGE16(0);
    __syncthreads();

    for (int k0 = 0; k0 < DM; k0 += 16) {
        int cur = (k0 >> 4) & 1;
        bool more = (k0 + 16 < DM);
        if (more) GEMM_LOAD16(k0 + 16);
        GEMM_MMA16(cur);
        if (more) {
            if (cur) GEMM_STAGE16(0); else GEMM_STAGE16(1);
        }
        __syncthreads();
    }

    #pragma unroll
    for (int i = 0; i < 4; i++) {
        int r0m = m0 + wm*64 + i*16 + g;
        #pragma unroll
        for (int j = 0; j < 8; j++) {
            int n = n0 + wn*64 + j*8 + tig*2;
            int h = n >> 6, kd = n & 63;
            float bvv0 = bias[n], bvv1 = bias[n+1];
            int b0i = r0m >> 11, s0 = r0m & (S_LEN-1);
            size_t base0 = (((size_t)(b0i*NH + h) * S_LEN + s0) << 6) + kd;
            out[base0]     = acc[i][j][0] + bvv0;
            out[base0 + 1] = acc[i][j][1] + bvv1;
            int r1m = r0m + 8;
            int b1i = r1m >> 11, s1 = r1m & (S_LEN-1);
            size_t base1 = (((size_t)(b1i*NH + h) * S_LEN + s1) << 6) + kd;
            out[base1]     = acc[i][j][2] + bvv0;
            out[base1 + 1] = acc[i][j][3] + bvv1;
        }
    }
}

__global__ __launch_bounds__(128, 2)
void out_gemm_f16(const float* __restrict__ Wo,
                  const float* __restrict__ bo,
                  float* __restrict__ C)
{
    __shared__ unsigned As[2][8][GS];
    __shared__ unsigned Bs[2][8][GS];

    const int KROW = HK, NROW = DM;
    int tid  = threadIdx.x;
    int w    = tid >> 5, lane = tid & 31;
    int g    = lane >> 2, tig = lane & 3;
    int wm   = w & 1, wn = w >> 1;
    int m0   = blockIdx.y * 128, n0 = blockIdx.x * 128;

    const float* aP = g_o + (size_t)m0 * KROW;
    const float* bP = Wo + n0;

    float4 av[4], bv0[2], bv1[2];
    float acc[4][8][4] = {};

    GEMM_LOAD16(0);
    GEMM_STAGE16(0);
    __syncthreads();

    for (int k0 = 0; k0 < HK; k0 += 16) {
        int cur = (k0 >> 4) & 1;
        bool more = (k0 + 16 < HK);
        if (more) GEMM_LOAD16(k0 + 16);
        GEMM_MMA16(cur);
        if (more) {
            if (cur) GEMM_STAGE16(0); else GEMM_STAGE16(1);
        }
        __syncthreads();
    }

    #pragma unroll
    for (int i = 0; i < 4; i++) {
        int r0m = m0 + wm*64 + i*16 + g;
        #pragma unroll
        for (int j = 0; j < 8; j++) {
            int n = n0 + wn*64 + j*8 + tig*2;
            float bvv0 = bo[n], bvv1 = bo[n+1];
            float2 o0 = make_float2(acc[i][j][0] + bvv0, acc[i][j][1] + bvv1);
            float2 o1 = make_float2(acc[i][j][2] + bvv0, acc[i][j][3] + bvv1);
            *(float2*)&C[(size_t)r0m * DM + n]       = o0;
            *(float2*)&C[(size_t)(r0m+8) * DM + n]   = o1;
        }
    }
}

// =====================================================================
// Flash attention, FP16 m16n8k16 MMA. q-tile 256, 8 warps (256 thr),
// M=32/warp (2 m-tiles), key tile 64, double-buffered K/V, one sync/iter.
// Grid = 8 x 32 = 256 CTAs -> exactly one wave at 2 CTA/SM.
// Smem (u32 words): KB0 0, KB1 2048, VB0 4096, VB1 6144, PA 8192 (1024 w/warp)
// total 16384 w = 64 KB -> 2 CTA/SM.
// =====================================================================
#define ATTN_SMEM (16384 * 4)
#define QSCALE 0.1803368801111204f   // 0.125 * log2(e)

#define ATTN_STAGE(bb, t0) do {                                               \
    _Pragma("unroll")                                                         \
    for (int f = 0; f < 4; f++) {                                             \
        int linear = f*256 + tid;                                             \
        int j = linear >> 4, d0 = (linear & 15) * 4;                          \
        float4 kv = *(const float4*)&kp[(size_t)((t0)+j)*HD + d0];            \
        {                                                                     \
            int kt = d0 >> 4, r = (d0 >> 3) & 1;                              \
            int nt = j >> 3;                                                  \
            int laneK = ((j & 7) << 2) + ((d0 & 7) >> 1);                     \
            unsigned* dst = &su[(bb)*2048 + ((((kt<<3)+nt)<<5) + laneK)*2 + r]; \
            dst[0] = h2pack(kv.x, kv.y);                                      \
            dst[2] = h2pack(kv.z, kv.w);                                      \
        }                                                                     \
        float4 vv = *(const float4*)&vp[(size_t)((t0)+j)*HD + d0];            \
        {                                                                     \
            int ktv = j >> 4, rv = (j >> 3) & 1;                              \
            int pairv = (j & 7) >> 1, ev = j & 1;                             \
            int ntv = d0 >> 3;                                                \
            __half* hb = (__half*)(su + 4096 + (bb)*2048);                    \
            int base = (((((ktv<<3)+ntv)<<5) + ((d0&7)<<2) + pairv)*2 + rv)*2 + ev; \
            hb[base     ] = __float2half(vv.x);                               \
            hb[base + 16] = __float2half(vv.y);                               \
            hb[base + 32] = __float2half(vv.z);                               \
            hb[base + 48] = __float2half(vv.w);                               \
        }                                                                     \
    }                                                                         \
} while (0)

__global__ __launch_bounds__(256, 2)
void attn_mma()
{
    extern __shared__ unsigned su[];
    unsigned* PA = su + 8192;

    int tid  = threadIdx.x;
    int w    = tid >> 5, lane = tid & 31;
    int g    = lane >> 2, tig = lane & 3;
    int bh   = blockIdx.y;
    int b    = bh >> 4, h = bh & 15;
    int q0   = blockIdx.x * 256;

    const float* qp = g_q + (size_t)bh * S_LEN * HD;
    const float* kp = g_k + (size_t)bh * S_LEN * HD;
    const float* vp = g_v + (size_t)bh * S_LEN * HD;

    // ---- stage Q (scratch overlay on whole smem), build prescaled fp16 frags ----
    float* Qs = (float*)su;    // 256x64 f32 = 64 KB
    #pragma unroll
    for (int it = 0; it < 16; it++) {
        int linear = it*256 + tid;
        int j = linear >> 4, d0 = (linear & 15) * 4;
        *(float4*)&Qs[j*64 + d0] = *(const float4*)&qp[(size_t)(q0 + j)*HD + d0];
    }
    __syncthreads();
    unsigned qf[2][4][4];   // [mi][kt][reg]
    #pragma unroll
    for (int mi = 0; mi < 2; mi++) {
        int rbase = 32*w + 16*mi;
        #pragma unroll
        for (int kt = 0; kt < 4; kt++) {
            const float* r0p = &Qs[(rbase+g  )*64 + kt*16];
            const float* r1p = &Qs[(rbase+g+8)*64 + kt*16];
            qf[mi][kt][0] = h2pack(r0p[2*tig  ]*QSCALE, r0p[2*tig+1]*QSCALE);
            qf[mi][kt][1] = h2pack(r1p[2*tig  ]*QSCALE, r1p[2*tig+1]*QSCALE);
            qf[mi][kt][2] = h2pack(r0p[8+2*tig]*QSCALE, r0p[8+2*tig+1]*QSCALE);
            qf[mi][kt][3] = h2pack(r1p[8+2*tig]*QSCALE, r1p[8+2*tig+1]*QSCALE);
        }
    }
    __syncthreads();

    ATTN_STAGE(0, 0);

    float o_acc[2][8][4] = {};
    float mrun[2][2], lrun[2][2];
    #pragma unroll
    for (int mi = 0; mi < 2; mi++) {
        mrun[mi][0] = -1e30f; mrun[mi][1] = -1e30f;
        lrun[mi][0] = 0.f;    lrun[mi][1] = 0.f;
    }

    #pragma unroll 1
    for (int it = 0; it < S_LEN/64; it++) {
        int cur = it & 1;
        __syncthreads();

        // ---- S = Q @ K^T ----
        const unsigned* KBc = su + cur*2048;
        float s[2][8][4] = {};
        #pragma unroll
        for (int kt = 0; kt < 4; kt++) {
            #pragma unroll
            for (int nt = 0; nt < 8; nt++) {
                unsigned b2[2];
                *(uint2*)b2 = *(const uint2*)&KBc[((((kt<<3)+nt)<<5) + lane)*2];
                mma_f16(s[0][nt], qf[0][kt], b2);
                mma_f16(s[1][nt], qf[1][kt], b2);
            }
        }

        // ---- online softmax (exp2 domain, quad-local), pack P to fp16 ----
        unsigned* paw = PA + w*1024;
        #pragma unroll
        for (int mi = 0; mi < 2; mi++) {
            float mx0 = mrun[mi][0], mx1 = mrun[mi][1];
            #pragma unroll
            for (int nt = 0; nt < 8; nt++) {
                mx0 = fmaxf(mx0, fmaxf(s[mi][nt][0], s[mi][nt][1]));
                mx1 = fmaxf(mx1, fmaxf(s[mi][nt][2], s[mi][nt][3]));
            }
            mx0 = fmaxf(mx0, __shfl_xor_sync(0xffffffffu, mx0, 1));
            mx0 = fmaxf(mx0, __shfl_xor_sync(0xffffffffu, mx0, 2));
            mx1 = fmaxf(mx1, __shfl_xor_sync(0xffffffffu, mx1, 1));
            mx1 = fmaxf(mx1, __shfl_xor_sync(0xffffffffu, mx1, 2));

            float alpha0 = exp2f(mrun[mi][0] - mx0);
            float alpha1 = exp2f(mrun[mi][1] - mx1);
            mrun[mi][0] = mx0; mrun[mi][1] = mx1;

            float sum0 = 0.f, sum1 = 0.f;
            unsigned* pam = paw + mi*512;
            #pragma unroll
            for (int nt = 0; nt < 8; nt++) {
                float p00 = exp2f(s[mi][nt][0] - mx0);
                float p01 = exp2f(s[mi][nt][1] - mx0);
                float p10 = exp2f(s[mi][nt][2] - mx1);
                float p11 = exp2f(s[mi][nt][3] - mx1);
                sum0 += p00 + p01;
                sum1 += p10 + p11;
                pam[((nt<<4) + g    )*4 + tig] = h2pack(p00, p01);
                pam[((nt<<4) + g + 8)*4 + tig] = h2pack(p10, p11);
            }
            sum0 += __shfl_xor_sync(0xffffffffu, sum0, 1);
            sum0 += __shfl_xor_sync(0xffffffffu, sum0, 2);
            sum1 += __shfl_xor_sync(0xffffffffu, sum1, 1);
            sum1 += __shfl_xor_sync(0xffffffffu, sum1, 2);
            lrun[mi][0] = lrun[mi][0]*alpha0 + sum0;
            lrun[mi][1] = lrun[mi][1]*alpha1 + sum1;

            #pragma unroll
            for (int nt = 0; nt < 8; nt++) {
                o_acc[mi][nt][0] *= alpha0; o_acc[mi][nt][1] *= alpha0;
                o_acc[mi][nt][2] *= alpha1; o_acc[mi][nt][3] *= alpha1;
            }
        }
        __syncwarp();

        // ---- O += P @ V ----
        const unsigned* VBc = su + 4096 + cur*2048;
        #pragma unroll
        for (int kt = 0; kt < 4; kt++) {
            unsigned pa0[4], pa1[4];
            pa0[0] = paw[(((2*kt  )<<4) + g    )*4 + tig];
            pa0[1] = paw[(((2*kt  )<<4) + g + 8)*4 + tig];
            pa0[2] = paw[(((2*kt+1)<<4) + g    )*4 + tig];
            pa0[3] = paw[(((2*kt+1)<<4) + g + 8)*4 + tig];
            pa1[0] = paw[512 + (((2*kt  )<<4) + g    )*4 + tig];
            pa1[1] = paw[512 + (((2*kt  )<<4) + g + 8)*4 + tig];
            pa1[2] = paw[512 + (((2*kt+1)<<4) + g    )*4 + tig];
            pa1[3] = paw[512 + (((2*kt+1)<<4) + g + 8)*4 + tig];
            #pragma unroll
            for (int nt = 0; nt < 8; nt++) {
                unsigned b2[2];
                *(uint2*)b2 = *(const uint2*)&VBc[((((kt<<3)+nt)<<5) + lane)*2];
                mma_f16(o_acc[0][nt], pa0, b2);
                mma_f16(o_acc[1][nt], pa1, b2);
            }
        }

        if (it + 1 < S_LEN/64) {
            ATTN_STAGE(1 - cur, (it + 1) * 64);
        }
    }

    // ---- epilogue ----
    #pragma unroll
    for (int mi = 0; mi < 2; mi++) {
        float inv0 = 1.0f / lrun[mi][0], inv1 = 1.0f / lrun[mi][1];
        int r0 = q0 + 32*w + 16*mi + g, r1 = r0 + 8;
        #pragma unroll
        for (int nt = 0; nt < 8; nt++) {
            int c = nt*8 + 2*tig;
            *(float2*)&g_o[(size_t)(b*S_LEN + r0)*HK + h*64 + c] =
                make_float2(o_acc[mi][nt][0]*inv0, o_acc[mi][nt][1]*inv0);
            *(float2*)&g_o[(size_t)(b*S_LEN + r1)*HK + h*64 + c] =
                make_float2(o_acc[mi][nt][2]*inv1, o_acc[mi][nt][3]*inv1);
        }
    }
}

// =====================================================================
extern "C" void kernel_launch(void* const* d_in, const int* in_sizes, int n_in,
                              void* d_out, int out_size)
{
    (void)in_sizes; (void)n_in; (void)out_size;
    const float* x  = (const float*)d_in[0];
    const float* Wq = (const float*)d_in[1];
    const float* bq = (const float*)d_in[2];
    const float* Wk = (const float*)d_in[3];
    const float* bk = (const float*)d_in[4];
    const float* Wv = (const float*)d_in[5];
    const float* bv = (const float*)d_in[6];
    const float* Wo = (const float*)d_in[7];
    const float* bo = (const float*)d_in[8];
    float* out = (float*)d_out;

    qkv_gemm_f16<<<dim3(HK/128, MROWS/128, 3), 128>>>(x, Wq, bq, Wk, bk, Wv, bv);

    cudaFuncSetAttribute(attn_mma, cudaFuncAttributeMaxDynamicSharedMemorySize, ATTN_SMEM);
    attn_mma<<<dim3(S_LEN/256, B_SZ*NH), 256, ATTN_SMEM>>>();

    out_gemm_f16<<<dim3(DM/128, MROWS/128), 128>>>(Wo, bo, out);
}

// round 17
// speedup vs baseline: 1.0616x; 1.0322x over previous
#include <cuda_runtime.h>
#include <cuda_fp16.h>

#define S_LEN   2048
#define B_SZ    2
#define DM      1024
#define NH      16
#define HD      64
#define HK      1024            // NH*HD
#define MROWS   (B_SZ*S_LEN)    // 4096

// ---------------- scratch (static device arrays; no allocation) -------------
__device__ float g_q[B_SZ*NH*S_LEN*HD];   // (b,h,s,k)
__device__ float g_k[B_SZ*NH*S_LEN*HD];
__device__ float g_v[B_SZ*NH*S_LEN*HD];
__device__ float g_o[MROWS*HK];           // (b,s,hk)

// ---------------- helpers ----------------------------------------------------
__device__ __forceinline__ unsigned h2pack(float a, float b) {
    __half2 t = __floats2half2_rn(a, b);
    return *(unsigned*)&t;
}

__device__ __forceinline__ void mma_f16(float* c, const unsigned* a, const unsigned* b) {
    asm volatile(
        "mma.sync.aligned.m16n8k16.row.col.f32.f16.f16.f32 "
        "{%0,%1,%2,%3}, {%4,%5,%6,%7}, {%8,%9}, {%0,%1,%2,%3};\n"
        : "+f"(c[0]), "+f"(c[1]), "+f"(c[2]), "+f"(c[3])
        : "r"(a[0]), "r"(a[1]), "r"(a[2]), "r"(a[3]),
          "r"(b[0]), "r"(b[1]));
}

// =====================================================================
// FP16 GEMM (R14 checkpoint): CTA 128x128, 128 threads (4 warps 2x2),
// warp tile 64x64, K-chunk 16, double-buffered.
// =====================================================================
#define GS 132

#define GEMM_STAGE16(buf) do {                                                \
    _Pragma("unroll")                                                         \
    for (int p = 0; p < 4; p++) {                                             \
        int la = p*128 + tid;                                                 \
        int row = la >> 2, kc = (la & 3) * 4;                                 \
        As[buf][(kc>>1)  ][row] = h2pack(av[p].x, av[p].y);                   \
        As[buf][(kc>>1)+1][row] = h2pack(av[p].z, av[p].w);                   \
    }                                                                         \
    _Pragma("unroll")                                                         \
    for (int p = 0; p < 2; p++) {                                             \
        int lb = p*128 + tid;                                                 \
        int kr2 = lb >> 5, nc = (lb & 31) * 4;                                \
        Bs[buf][kr2][nc+0] = h2pack(bv0[p].x, bv1[p].x);                      \
        Bs[buf][kr2][nc+1] = h2pack(bv0[p].y, bv1[p].y);                      \
        Bs[buf][kr2][nc+2] = h2pack(bv0[p].z, bv1[p].z);                      \
        Bs[buf][kr2][nc+3] = h2pack(bv0[p].w, bv1[p].w);                      \
    }                                                                         \
} while (0)

#define GEMM_LOAD16(kbase) do {                                               \
    _Pragma("unroll")                                                         \
    for (int p = 0; p < 4; p++) {                                             \
        int la = p*128 + tid;                                                 \
        av[p] = *(const float4*)&aP[(size_t)(la >> 2) * KROW + (kbase) + (la & 3) * 4]; \
    }                                                                         \
    _Pragma("unroll")                                                         \
    for (int p = 0; p < 2; p++) {                                             \
        int lb = p*128 + tid;                                                 \
        int kr2 = lb >> 5, nc = (lb & 31) * 4;                                \
        bv0[p] = *(const float4*)&bP[(size_t)((kbase) + 2*kr2    ) * NROW + nc]; \
        bv1[p] = *(const float4*)&bP[(size_t)((kbase) + 2*kr2 + 1) * NROW + nc]; \
    }                                                                         \
} while (0)

#define GEMM_MMA16(buf) do {                                                  \
    unsigned af[4][4], bf[8][2];                                              \
    _Pragma("unroll")                                                         \
    for (int i = 0; i < 4; i++) {                                             \
        int mb = wm*64 + i*16;                                                \
        af[i][0] = As[buf][tig  ][mb+g];                                      \
        af[i][1] = As[buf][tig  ][mb+g+8];                                    \
        af[i][2] = As[buf][tig+4][mb+g];                                      \
        af[i][3] = As[buf][tig+4][mb+g+8];                                    \
    }                                                                         \
    _Pragma("unroll")                                                         \
    for (int j = 0; j < 8; j++) {                                             \
        int nb = wn*64 + j*8;                                                 \
        bf[j][0] = Bs[buf][tig  ][nb+g];                                      \
        bf[j][1] = Bs[buf][tig+4][nb+g];                                      \
    }                                                                         \
    _Pragma("unroll")                                                         \
    for (int i = 0; i < 4; i++)                                               \
        _Pragma("unroll")                                                     \
        for (int j = 0; j < 8; j++)                                           \
            mma_f16(acc[i][j], af[i], bf[j]);                                 \
} while (0)

__global__ __launch_bounds__(128, 2)
void qkv_gemm_f16(const float* __restrict__ x,
                  const float* __restrict__ Wq, const float* __restrict__ bq,
                  const float* __restrict__ Wk, const float* __restrict__ bk,
                  const float* __restrict__ Wv, const float* __restrict__ bv)
{
    __shared__ unsigned As[2][8][GS];
    __shared__ unsigned Bs[2][8][GS];

    const float* W; const float* bias; float* out;
    int z = blockIdx.z;
    if (z == 0)      { W = Wq; bias = bq; out = g_q; }
    else if (z == 1) { W = Wk; bias = bk; out = g_k; }
    else             { W = Wv; bias = bv; out = g_v; }

    const int KROW = DM, NROW = HK;
    int tid  = threadIdx.x;
    int w    = tid >> 5, lane = tid & 31;
    int g    = lane >> 2, tig = lane & 3;
    int wm   = w & 1, wn = w >> 1;
    int m0   = blockIdx.y * 128, n0 = blockIdx.x * 128;

    const float* aP = x + (size_t)m0 * KROW;
    const float* bP = W + n0;

    float4 av[4], bv0[2], bv1[2];
    float acc[4][8][4] = {};

    GEMM_LOAD16(0);
    GEMM_STAGE16(0);
    __syncthreads();

    for (int k0 = 0; k0 < DM; k0 += 16) {
        int cur = (k0 >> 4) & 1;
        bool more = (k0 + 16 < DM);
        if (more) GEMM_LOAD16(k0 + 16);
        GEMM_MMA16(cur);
        if (more) {
            if (cur) GEMM_STAGE16(0); else GEMM_STAGE16(1);
        }
        __syncthreads();
    }

    #pragma unroll
    for (int i = 0; i < 4; i++) {
        int r0m = m0 + wm*64 + i*16 + g;
        #pragma unroll
        for (int j = 0; j < 8; j++) {
            int n = n0 + wn*64 + j*8 + tig*2;
            int h = n >> 6, kd = n & 63;
            float bvv0 = bias[n], bvv1 = bias[n+1];
            int b0i = r0m >> 11, s0 = r0m & (S_LEN-1);
            size_t base0 = (((size_t)(b0i*NH + h) * S_LEN + s0) << 6) + kd;
            out[base0]     = acc[i][j][0] + bvv0;
            out[base0 + 1] = acc[i][j][1] + bvv1;
            int r1m = r0m + 8;
            int b1i = r1m >> 11, s1 = r1m & (S_LEN-1);
            size_t base1 = (((size_t)(b1i*NH + h) * S_LEN + s1) << 6) + kd;
            out[base1]     = acc[i][j][2] + bvv0;
            out[base1 + 1] = acc[i][j][3] + bvv1;
        }
    }
}

__global__ __launch_bounds__(128, 2)
void out_gemm_f16(const float* __restrict__ Wo,
                  const float* __restrict__ bo,
                  float* __restrict__ C)
{
    __shared__ unsigned As[2][8][GS];
    __shared__ unsigned Bs[2][8][GS];

    const int KROW = HK, NROW = DM;
    int tid  = threadIdx.x;
    int w    = tid >> 5, lane = tid & 31;
    int g    = lane >> 2, tig = lane & 3;
    int wm   = w & 1, wn = w >> 1;
    int m0   = blockIdx.y * 128, n0 = blockIdx.x * 128;

    const float* aP = g_o + (size_t)m0 * KROW;
    const float* bP = Wo + n0;

    float4 av[4], bv0[2], bv1[2];
    float acc[4][8][4] = {};

    GEMM_LOAD16(0);
    GEMM_STAGE16(0);
    __syncthreads();

    for (int k0 = 0; k0 < HK; k0 += 16) {
        int cur = (k0 >> 4) & 1;
        bool more = (k0 + 16 < HK);
        if (more) GEMM_LOAD16(k0 + 16);
        GEMM_MMA16(cur);
        if (more) {
            if (cur) GEMM_STAGE16(0); else GEMM_STAGE16(1);
        }
        __syncthreads();
    }

    #pragma unroll
    for (int i = 0; i < 4; i++) {
        int r0m = m0 + wm*64 + i*16 + g;
        #pragma unroll
        for (int j = 0; j < 8; j++) {
            int n = n0 + wn*64 + j*8 + tig*2;
            float bvv0 = bo[n], bvv1 = bo[n+1];
            float2 o0 = make_float2(acc[i][j][0] + bvv0, acc[i][j][1] + bvv1);
            float2 o1 = make_float2(acc[i][j][2] + bvv0, acc[i][j][3] + bvv1);
            *(float2*)&C[(size_t)r0m * DM + n]       = o0;
            *(float2*)&C[(size_t)(r0m+8) * DM + n]   = o1;
        }
    }
}

// =====================================================================
// Flash attention, FP16 m16n8k16 MMA, q-tile 128, 4 warps (128 thr),
// M=32/warp, key tile 64, double-buffered K/V, one sync/iter.
// P NEVER TOUCHES SMEM: QK accumulator frags are repacked in registers
// into PV A-frags (layouts are lane-identical).
// Smem (u32 words): KB0 0, KB1 2048, VB0 4096, VB1 6144. Total 32 KB.
// =====================================================================
#define ATTN_SMEM (8192 * 4)
#define QSCALE 0.1803368801111204f   // 0.125 * log2(e)

#define ATTN_STAGE(bb, t0) do {                                               \
    _Pragma("unroll")                                                         \
    for (int f = 0; f < 8; f++) {                                             \
        int linear = f*128 + tid;                                             \
        int j = linear >> 4, d0 = (linear & 15) * 4;                          \
        float4 kv = *(const float4*)&kp[(size_t)((t0)+j)*HD + d0];            \
        {                                                                     \
            int kt = d0 >> 4, r = (d0 >> 3) & 1;                              \
            int nt = j >> 3;                                                  \
            int laneK = ((j & 7) << 2) + ((d0 & 7) >> 1);                     \
            unsigned* dst = &su[(bb)*2048 + ((((kt<<3)+nt)<<5) + laneK)*2 + r]; \
            dst[0] = h2pack(kv.x, kv.y);                                      \
            dst[2] = h2pack(kv.z, kv.w);                                      \
        }                                                                     \
        float4 vv = *(const float4*)&vp[(size_t)((t0)+j)*HD + d0];            \
        {                                                                     \
            int ktv = j >> 4, rv = (j >> 3) & 1;                              \
            int pairv = (j & 7) >> 1, ev = j & 1;                             \
            int ntv = d0 >> 3;                                                \
            __half* hb = (__half*)(su + 4096 + (bb)*2048);                    \
            int base = (((((ktv<<3)+ntv)<<5) + ((d0&7)<<2) + pairv)*2 + rv)*2 + ev; \
            hb[base     ] = __float2half(vv.x);                               \
            hb[base + 16] = __float2half(vv.y);                               \
            hb[base + 32] = __float2half(vv.z);                               \
            hb[base + 48] = __float2half(vv.w);                               \
        }                                                                     \
    }                                                                         \
} while (0)

__global__ __launch_bounds__(128, 2)
void attn_mma()
{
    extern __shared__ unsigned su[];

    int tid  = threadIdx.x;
    int w    = tid >> 5, lane = tid & 31;
    int g    = lane >> 2, tig = lane & 3;
    int bh   = blockIdx.y;
    int b    = bh >> 4, h = bh & 15;
    int q0   = blockIdx.x * 128;

    const float* qp = g_q + (size_t)bh * S_LEN * HD;
    const float* kp = g_k + (size_t)bh * S_LEN * HD;
    const float* vp = g_v + (size_t)bh * S_LEN * HD;

    // ---- stage Q (scratch overlay on KB/VB), build prescaled fp16 A-frags ----
    float* Qs = (float*)su;    // 128x64 f32 = 32 KB (exactly the smem region)
    #pragma unroll
    for (int it = 0; it < 16; it++) {
        int linear = it*128 + tid;
        int j = linear >> 4, d0 = (linear & 15) * 4;
        *(float4*)&Qs[j*64 + d0] = *(const float4*)&qp[(size_t)(q0 + j)*HD + d0];
    }
    __syncthreads();
    unsigned qf[2][4][4];   // [mi][kt][reg]
    #pragma unroll
    for (int mi = 0; mi < 2; mi++) {
        int rbase = 32*w + 16*mi;
        #pragma unroll
        for (int kt = 0; kt < 4; kt++) {
            const float* r0p = &Qs[(rbase+g  )*64 + kt*16];
            const float* r1p = &Qs[(rbase+g+8)*64 + kt*16];
            qf[mi][kt][0] = h2pack(r0p[2*tig  ]*QSCALE, r0p[2*tig+1]*QSCALE);
            qf[mi][kt][1] = h2pack(r1p[2*tig  ]*QSCALE, r1p[2*tig+1]*QSCALE);
            qf[mi][kt][2] = h2pack(r0p[8+2*tig]*QSCALE, r0p[8+2*tig+1]*QSCALE);
            qf[mi][kt][3] = h2pack(r1p[8+2*tig]*QSCALE, r1p[8+2*tig+1]*QSCALE);
        }
    }
    __syncthreads();

    ATTN_STAGE(0, 0);

    float o_acc[2][8][4] = {};
    float mrun[2][2], lrun[2][2];
    #pragma unroll
    for (int mi = 0; mi < 2; mi++) {
        mrun[mi][0] = -1e30f; mrun[mi][1] = -1e30f;
        lrun[mi][0] = 0.f;    lrun[mi][1] = 0.f;
    }

    #pragma unroll 1
    for (int it = 0; it < S_LEN/64; it++) {
        int cur = it & 1;
        __syncthreads();

        // ---- S = Q @ K^T ----
        const unsigned* KBc = su + cur*2048;
        float s[2][8][4] = {};
        #pragma unroll
        for (int kt = 0; kt < 4; kt++) {
            #pragma unroll
            for (int nt = 0; nt < 8; nt++) {
                unsigned b2[2];
                *(uint2*)b2 = *(const uint2*)&KBc[((((kt<<3)+nt)<<5) + lane)*2];
                mma_f16(s[0][nt], qf[0][kt], b2);
                mma_f16(s[1][nt], qf[1][kt], b2);
            }
        }

        // ---- online softmax (exp2 domain, quad-local); p overwrites s ----
        #pragma unroll
        for (int mi = 0; mi < 2; mi++) {
            float mx0 = mrun[mi][0], mx1 = mrun[mi][1];
            #pragma unroll
            for (int nt = 0; nt < 8; nt++) {
                mx0 = fmaxf(mx0, fmaxf(s[mi][nt][0], s[mi][nt][1]));
                mx1 = fmaxf(mx1, fmaxf(s[mi][nt][2], s[mi][nt][3]));
            }
            mx0 = fmaxf(mx0, __shfl_xor_sync(0xffffffffu, mx0, 1));
            mx0 = fmaxf(mx0, __shfl_xor_sync(0xffffffffu, mx0, 2));
            mx1 = fmaxf(mx1, __shfl_xor_sync(0xffffffffu, mx1, 1));
            mx1 = fmaxf(mx1, __shfl_xor_sync(0xffffffffu, mx1, 2));

            float alpha0 = exp2f(mrun[mi][0] - mx0);
            float alpha1 = exp2f(mrun[mi][1] - mx1);
            mrun[mi][0] = mx0; mrun[mi][1] = mx1;

            float sum0 = 0.f, sum1 = 0.f;
            #pragma unroll
            for (int nt = 0; nt < 8; nt++) {
                float p00 = exp2f(s[mi][nt][0] - mx0);
                float p01 = exp2f(s[mi][nt][1] - mx0);
                float p10 = exp2f(s[mi][nt][2] - mx1);
                float p11 = exp2f(s[mi][nt][3] - mx1);
                sum0 += p00 + p01;
                sum1 += p10 + p11;
                s[mi][nt][0] = p00; s[mi][nt][1] = p01;
                s[mi][nt][2] = p10; s[mi][nt][3] = p11;
            }
            sum0 += __shfl_xor_sync(0xffffffffu, sum0, 1);
            sum0 += __shfl_xor_sync(0xffffffffu, sum0, 2);
            sum1 += __shfl_xor_sync(0xffffffffu, sum1, 1);
            sum1 += __shfl_xor_sync(0xffffffffu, sum1, 2);
            lrun[mi][0] = lrun[mi][0]*alpha0 + sum0;
            lrun[mi][1] = lrun[mi][1]*alpha1 + sum1;

            #pragma unroll
            for (int nt = 0; nt < 8; nt++) {
                o_acc[mi][nt][0] *= alpha0; o_acc[mi][nt][1] *= alpha0;
                o_acc[mi][nt][2] *= alpha1; o_acc[mi][nt][3] *= alpha1;
            }
        }

        // ---- O += P @ V: PV A-frags packed in registers from s ----
        const unsigned* VBc = su + 4096 + cur*2048;
        #pragma unroll
        for (int kt = 0; kt < 4; kt++) {
            unsigned pa0[4], pa1[4];
            pa0[0] = h2pack(s[0][2*kt  ][0], s[0][2*kt  ][1]);
            pa0[1] = h2pack(s[0][2*kt  ][2], s[0][2*kt  ][3]);
            pa0[2] = h2pack(s[0][2*kt+1][0], s[0][2*kt+1][1]);
            pa0[3] = h2pack(s[0][2*kt+1][2], s[0][2*kt+1][3]);
            pa1[0] = h2pack(s[1][2*kt  ][0], s[1][2*kt  ][1]);
            pa1[1] = h2pack(s[1][2*kt  ][2], s[1][2*kt  ][3]);
            pa1[2] = h2pack(s[1][2*kt+1][0], s[1][2*kt+1][1]);
            pa1[3] = h2pack(s[1][2*kt+1][2], s[1][2*kt+1][3]);
            #pragma unroll
            for (int nt = 0; nt < 8; nt++) {
                unsigned b2[2];
                *(uint2*)b2 = *(const uint2*)&VBc[((((kt<<3)+nt)<<5) + lane)*2];
                mma_f16(o_acc[0][nt], pa0, b2);
                mma_f16(o_acc[1][nt], pa1, b2);
            }
        }

        if (it + 1 < S_LEN/64) {
            ATTN_STAGE(1 - cur, (it + 1) * 64);
        }
    }

    // ---- epilogue ----
    #pragma unroll
    for (int mi = 0; mi < 2; mi++) {
        float inv0 = 1.0f / lrun[mi][0], inv1 = 1.0f / lrun[mi][1];
        int r0 = q0 + 32*w + 16*mi + g, r1 = r0 + 8;
        #pragma unroll
        for (int nt = 0; nt < 8; nt++) {
            int c = nt*8 + 2*tig;
            *(float2*)&g_o[(size_t)(b*S_LEN + r0)*HK + h*64 + c] =
                make_float2(o_acc[mi][nt][0]*inv0, o_acc[mi][nt][1]*inv0);
            *(float2*)&g_o[(size_t)(b*S_LEN + r1)*HK + h*64 + c] =
                make_float2(o_acc[mi][nt][2]*inv1, o_acc[mi][nt][3]*inv1);
        }
    }
}

// =====================================================================
extern "C" void kernel_launch(void* const* d_in, const int* in_sizes, int n_in,
                              void* d_out, int out_size)
{
    (void)in_sizes; (void)n_in; (void)out_size;
    const float* x  = (const float*)d_in[0];
    const float* Wq = (const float*)d_in[1];
    const float* bq = (const float*)d_in[2];
    const float* Wk = (const float*)d_in[3];
    const float* bk = (const float*)d_in[4];
    const float* Wv = (const float*)d_in[5];
    const float* bv = (const float*)d_in[6];
    const float* Wo = (const float*)d_in[7];
    const float* bo = (const float*)d_in[8];
    float* out = (float*)d_out;

    qkv_gemm_f16<<<dim3(HK/128, MROWS/128, 3), 128>>>(x, Wq, bq, Wk, bk, Wv, bv);

    cudaFuncSetAttribute(attn_mma, cudaFuncAttributeMaxDynamicSharedMemorySize, ATTN_SMEM);
    attn_mma<<<dim3(S_LEN/128, B_SZ*NH), 128, ATTN_SMEM>>>();

    out_gemm_f16<<<dim3(DM/128, MROWS/128), 128>>>(Wo, bo, out);
}